// round 15
// baseline (speedup 1.0000x reference)
#include <cuda_runtime.h>
#include <math.h>

// ---------------------------------------------------------------------------
// Augmentation3d: affine (Rodrigues * scale + shift) + smoothed random
// displacement field + trilinear grid_sample, cropped to center 128^3.
//
// Inputs (metadata order):
//   d_in[0] vol   : (4,1,160,160,160) f32
//   d_in[1] rot   : (4,3) f32
//   d_in[2] scale : (4,3) f32
//   d_in[3] shift : (4,3) f32
//   d_in[4] dz    : (1,1,15,15,15) f32
//   d_in[5] dy    : (1,1,15,15,15) f32
//   d_in[6] dx    : (1,1,15,15,15) f32
// Output: (4,1,128,128,128) f32
// ---------------------------------------------------------------------------

#define VD 160
#define VD2 (VD * VD)
#define VSZ (VD * VD * VD)
#define OD 128
#define CROP0 16            // (160-128)/2
#define FDIM 15
#define FN (FDIM * FDIM * FDIM)   // 3375
#define FS 11
#define FS3 (FS * FS * FS)        // 1331
#define NBATCH 4
#define KZ 16                // z-slices per block in sample kernel
#define KB 4                 // kz batch size (loads hoisted per batch)
#define SCLF (11.0f / 160.0f)
#define FULLM 0xffffffffu

__device__ float g_field[3][FS3];      // cropped smoothed fields (dz, dy, dx)
__device__ float g_theta[NBATCH * 12]; // per batch: 3 rows of [A0 A1 A2 shift]

// ---------------------------------------------------------------------------
// Prep kernel: 3 blocks (one per field). The 4x clamped 5-tap box smooth is a
// fixed linear operator per axis -> build B^4 (15x15) in smem (redundantly per
// block, it's tiny), then apply as three small separable matmuls with the
// [2:13] crop folded in. Block 0 also computes theta for the 4 batches.
// ---------------------------------------------------------------------------
__global__ void __launch_bounds__(1024) prep_kernel(
        const float* __restrict__ rot,
        const float* __restrict__ scale,
        const float* __restrict__ shift,
        const float* __restrict__ dz,
        const float* __restrict__ dy,
        const float* __restrict__ dx) {
    __shared__ float Bm[FDIM][FDIM];   // clamped box matrix
    __shared__ float B2[FDIM][FDIM];   // B^2
    __shared__ float M[FS][FDIM];      // rows 2..12 of B^4 (crop folded)
    __shared__ float bufA[FN];         // 3375
    __shared__ float bufB[FS * FDIM * FDIM]; // 2475

    const int f = blockIdx.x;
    const float* raw = (f == 0) ? dz : ((f == 1) ? dy : dx);
    const int t = threadIdx.x;
    const int NT = blockDim.x;

    // --- theta (block 0, threads 0..3) ---
    if (f == 0 && t < NBATCH) {
        const int nb = t;
        float rx = rot[nb * 3 + 0], ry = rot[nb * 3 + 1], rz = rot[nb * 3 + 2];
        float t2 = rx * rx + ry * ry + rz * rz;
        float th = sqrtf(fmaxf(t2, 1e-6f));
        float inv = 1.0f / (th + 1e-6f);
        float wx = rx * inv, wy = ry * inv, wz = rz * inv;
        float c = cosf(th), s = sinf(th), k = 1.0f - c;
        float R[9];
        if (t2 > 1e-6f) {
            R[0] = c + wx * wx * k;      R[1] = wx * wy * k - wz * s; R[2] = wy * s + wx * wz * k;
            R[3] = wz * s + wx * wy * k; R[4] = c + wy * wy * k;      R[5] = -wx * s + wy * wz * k;
            R[6] = -wy * s + wx * wz * k; R[7] = wx * s + wy * wz * k; R[8] = c + wz * wz * k;
        } else {
            R[0] = 1.0f; R[1] = -rz;  R[2] = ry;
            R[3] = rz;   R[4] = 1.0f; R[5] = -rx;
            R[6] = -ry;  R[7] = rx;   R[8] = 1.0f;
        }
        #pragma unroll
        for (int i = 0; i < 3; ++i) {
            #pragma unroll
            for (int j = 0; j < 3; ++j)
                g_theta[nb * 12 + i * 4 + j] = R[i * 3 + j] * scale[nb * 3 + j];
            g_theta[nb * 12 + i * 4 + 3] = shift[nb * 3 + i];
        }
    }

    // --- build B (clamped box), B^2, then M = (B^4)[2:13,:] ---
    if (t < FDIM * FDIM) {
        int i = t / FDIM, j = t % FDIM;
        int cnt = 0;
        #pragma unroll
        for (int d = -2; d <= 2; ++d) {
            int k = i + d;
            k = k < 0 ? 0 : (k > FDIM - 1 ? FDIM - 1 : k);
            cnt += (k == j);
        }
        Bm[i][j] = 0.2f * (float)cnt;
    }
    // load + pre-scale raw field concurrently
    for (int i = t; i < FN; i += NT)
        bufA[i] = (raw[i] - 0.5f) * 4.0f;       // (raw-0.5)*2*ALPHA
    __syncthreads();
    if (t < FDIM * FDIM) {
        int i = t / FDIM, j = t % FDIM;
        float s = 0.0f;
        #pragma unroll
        for (int k = 0; k < FDIM; ++k) s += Bm[i][k] * Bm[k][j];
        B2[i][j] = s;
    }
    __syncthreads();
    if (t < FS * FDIM) {
        int i = t / FDIM + 2, j = t % FDIM;   // rows 2..12
        float s = 0.0f;
        #pragma unroll
        for (int k = 0; k < FDIM; ++k) s += B2[i][k] * B2[k][j];
        M[i - 2][j] = s;
    }
    __syncthreads();

    // z-pass: [15,15,15] -> [11,15,15]
    for (int i = t; i < FS * FDIM * FDIM; i += NT) {
        int xy = i % (FDIM * FDIM);
        int zo = i / (FDIM * FDIM);
        float s = 0.0f;
        #pragma unroll
        for (int k = 0; k < FDIM; ++k)
            s += M[zo][k] * bufA[k * FDIM * FDIM + xy];
        bufB[i] = s;
    }
    __syncthreads();
    // y-pass: [11,15,15] -> [11,11,15] (into bufA)
    for (int i = t; i < FS * FS * FDIM; i += NT) {
        int x = i % FDIM;
        int yo = (i / FDIM) % FS;
        int zo = i / (FDIM * FS);
        float s = 0.0f;
        #pragma unroll
        for (int k = 0; k < FDIM; ++k)
            s += M[yo][k] * bufB[zo * FDIM * FDIM + k * FDIM + x];
        bufA[zo * FS * FDIM + yo * FDIM + x] = s;
    }
    __syncthreads();
    // x-pass: [11,11,15] -> [11,11,11] (to global)
    for (int i = t; i < FS3; i += NT) {
        int xo = i % FS;
        int yo = (i / FS) % FS;
        int zo = i / (FS * FS);
        float s = 0.0f;
        #pragma unroll
        for (int k = 0; k < FDIM; ++k)
            s += M[xo][k] * bufA[zo * FS * FDIM + yo * FDIM + k];
        g_field[f][i] = s;
    }
}

// ---------------------------------------------------------------------------
// Main kernel: block = one x-row (128 threads) x KZ=16 z-slices. Field rows
// staged behind one __syncthreads. kz runs in KB=4 batches, loads hoisted.
// Gather-reuse, two axes:
//  - z-face reuse: source z advances ~1 per kz -> iteration j's TOP face is
//    usually iteration j-1's BOTTOM face (carried in registers).
//  - x-face reuse (intra-warp): source x advances ~1 per lane -> lane i's
//    RIGHT-face corners usually equal lane i+1's LEFT-face corners; resolved
//    left values are shfl'd down and right-face LDGs predicated off.
// Both predicates are exact coordinate matches -> bit-identical values.
// Fast path requires whole-warp interior (one vote per KB batch).
// ---------------------------------------------------------------------------
__global__ void __launch_bounds__(128) sample_kernel(
    const float* __restrict__ vol, float* __restrict__ out) {
    const int x  = threadIdx.x;              // 0..127
    const int y  = blockIdx.y;               // 0..127
    const int g  = blockIdx.z;               // n*(128/KZ) + zgrp
    const int n  = g >> 3;                   // 128/KZ = 8
    const int zb = (g & 7) * KZ;             // output z base

    const int xg  = x + CROP0;
    const int yg  = y + CROP0;
    const int zgb = zb + CROP0;

    __shared__ float4 Gf4[KZ][12];           // staged field rows (x80)

    // field y (block-uniform, loop-invariant)
    const float ysrc = fmaf((float)yg + 0.5f, SCLF, -0.5f);
    const int   iy0  = (int)ysrc;
    const float wy   = ysrc - (float)iy0;

    // ---- stage all KZ field rows: 3 fields x 11 x-cells x KZ z = 528 items ----
    for (int s = threadIdx.x; s < 3 * FS * KZ; s += 128) {
        int f2 = s / (FS * KZ);              // field 0..2
        int r  = s - f2 * FS * KZ;
        int kz = r / FS;
        int ix = r - kz * FS;
        float zsrc = fmaf((float)(zgb + kz) + 0.5f, SCLF, -0.5f);
        int   iz0  = (int)zsrc;
        float wz   = zsrc - (float)iz0;
        const float* F = g_field[f2] + (iz0 * FS + iy0) * FS + ix;
        float v00 = __ldg(F);
        float v01 = __ldg(F + FS);
        float v10 = __ldg(F + FS * FS);
        float v11 = __ldg(F + FS * FS + FS);
        float a = fmaf(v01 - v00, wy, v00);
        float b = fmaf(v11 - v10, wy, v10);
        ((float*)&Gf4[kz][ix])[f2] = fmaf(b - a, wz, a) * 80.0f;
    }

    // theta (broadcast loads, loop-invariant) — overlaps with staging
    const float* T = g_theta + n * 12;
    const float t0 = __ldg(T + 0), t1 = __ldg(T + 1), t2 = __ldg(T + 2),  t3  = __ldg(T + 3);
    const float t4 = __ldg(T + 4), t5 = __ldg(T + 5), t6 = __ldg(T + 6),  t7  = __ldg(T + 7);
    const float t8 = __ldg(T + 8), t9 = __ldg(T + 9), t10= __ldg(T + 10), t11 = __ldg(T + 11);

    const float C2 = 2.0f / 160.0f;
    const float C1 = 1.0f / 160.0f - 1.0f;
    const float xv  = fmaf((float)xg,  C2, C1);
    const float yv  = fmaf((float)yg,  C2, C1);
    const float zv0 = fmaf((float)zgb, C2, C1);

    // px = 80*gx + 79.5 ; per-z step of 80*t*(2/160) = t folds to +kz*t2 etc.
    const float bx = fmaf(80.0f, fmaf(t0, xv, fmaf(t1, yv, fmaf(t2,  zv0, t3 ))), 79.5f);
    const float by = fmaf(80.0f, fmaf(t4, xv, fmaf(t5, yv, fmaf(t6,  zv0, t7 ))), 79.5f);
    const float bz = fmaf(80.0f, fmaf(t8, xv, fmaf(t9, yv, fmaf(t10, zv0, t11))), 79.5f);

    // field x-cell (per thread, loop-invariant; interior -> no clamp needed)
    const float xsrc = fmaf((float)xg + 0.5f, SCLF, -0.5f);   // in (0.6, 9.4)
    const int   ix0  = (int)xsrc;
    const float wxf  = xsrc - (float)ix0;

    const float* v  = vol + (size_t)n * VSZ;
    float*       op = out + (((size_t)(n * OD + zb)) * OD + y) * OD + x;

    // z-carry: coords + RESOLVED bottom-face values of last processed iter
    int   xp = 0, yp = 0, zp = -0x40000000;   // impossible -> no reuse on first
    float pb0 = 0.0f, pb1 = 0.0f, pb2 = 0.0f, pb3 = 0.0f;

    __syncthreads();   // single barrier: staged rows ready

    #pragma unroll 1
    for (int b = 0; b < KZ; b += KB) {
        float axA[KB], ayA[KB], azA[KB];
        int   x0A[KB], y0A[KB], z0A[KB];
        int   ruA[KB], shA[KB];
        const float* vbA[KB];
        int allin = 1;

        #pragma unroll
        for (int j = 0; j < KB; ++j) {
            int kz = b + j;
            float4 A = Gf4[kz][ix0];
            float4 B = Gf4[kz][ix0 + 1];
            float kf = (float)kz;
            float px = fmaf(kf, t2,  bx) + fmaf(B.x - A.x, wxf, A.x);
            float py = fmaf(kf, t6,  by) + fmaf(B.y - A.y, wxf, A.y);
            float pz = fmaf(kf, t10, bz) + fmaf(B.z - A.z, wxf, A.z);
            int x0 = __float2int_rd(px);  axA[j] = px - (float)x0;
            int y0 = __float2int_rd(py);  ayA[j] = py - (float)y0;
            int z0 = __float2int_rd(pz);  azA[j] = pz - (float)z0;
            x0A[j] = x0; y0A[j] = y0; z0A[j] = z0;
            vbA[j] = v + (z0 * VD + y0) * VD + x0;
            // z-reuse predicate (vs previous kz of this lane)
            int px_ = (j == 0) ? xp : x0A[j - 1];
            int py_ = (j == 0) ? yp : y0A[j - 1];
            int pz_ = (j == 0) ? zp : z0A[j - 1];
            ruA[j] = (x0 == px_) & (y0 == py_) & (z0 == pz_ + 1);
            // x-share predicate (vs lane+1, same kz); lane 31 never shares
            int xn = __shfl_down_sync(FULLM, x0, 1);
            int yn = __shfl_down_sync(FULLM, y0, 1);
            int zn = __shfl_down_sync(FULLM, z0, 1);
            shA[j] = ((x & 31) != 31) & (xn == x0 + 1) & (yn == y0) & (zn == z0);
            allin &= ((unsigned)x0 < (unsigned)(VD - 1)) &
                     ((unsigned)y0 < (unsigned)(VD - 1)) &
                     ((unsigned)z0 < (unsigned)(VD - 1));
        }

        if (__all_sync(FULLM, allin)) {
            // fast path: left-face loads always (bottom) / unless z-reused
            // (top); right-face loads predicated off when x-shared.
            float tl0[KB], tl1[KB], tr0[KB], tr1[KB];   // top: L-y0, L-y1, R-y0, R-y1
            float bl0[KB], bl1[KB], br0[KB], br1[KB];   // bottom
            #pragma unroll
            for (int j = 0; j < KB; ++j) {
                const float* vb = vbA[j];
                int ru = ruA[j], sh = shA[j];
                bl0[j] = __ldg(vb + VD2);
                bl1[j] = __ldg(vb + VD2 + VD);
                br0[j] = 0.0f; br1[j] = 0.0f;
                if (!sh) { br0[j] = __ldg(vb + VD2 + 1); br1[j] = __ldg(vb + VD2 + VD + 1); }
                tl0[j] = 0.0f; tl1[j] = 0.0f; tr0[j] = 0.0f; tr1[j] = 0.0f;
                if (!ru) {
                    tl0[j] = __ldg(vb);  tl1[j] = __ldg(vb + VD);
                    if (!sh) { tr0[j] = __ldg(vb + 1); tr1[j] = __ldg(vb + VD + 1); }
                }
            }
            #pragma unroll
            for (int j = 0; j < KB; ++j) {
                int ru = ruA[j], sh = shA[j];
                // resolve left values (z-carry), then shfl to serve right values
                float v000 = ru ? pb0 : tl0[j];
                float v010 = ru ? pb2 : tl1[j];
                float v100 = bl0[j];
                float v110 = bl1[j];
                float v000n = __shfl_down_sync(FULLM, v000, 1);
                float v010n = __shfl_down_sync(FULLM, v010, 1);
                float v100n = __shfl_down_sync(FULLM, v100, 1);
                float v110n = __shfl_down_sync(FULLM, v110, 1);
                float v001 = ru ? pb1 : (sh ? v000n : tr0[j]);
                float v011 = ru ? pb3 : (sh ? v010n : tr1[j]);
                float v101 = sh ? v100n : br0[j];
                float v111 = sh ? v110n : br1[j];
                float ax = axA[j], ay = ayA[j], az = azA[j];
                float c00 = fmaf(v001 - v000, ax, v000);
                float c01 = fmaf(v011 - v010, ax, v010);
                float c10 = fmaf(v101 - v100, ax, v100);
                float c11 = fmaf(v111 - v110, ax, v110);
                float c0  = fmaf(c01 - c00, ay, c00);
                float c1  = fmaf(c11 - c10, ay, c10);
                op[(b + j) * OD * OD] = fmaf(c1 - c0, az, c0);
                pb0 = v100; pb1 = v101; pb2 = v110; pb3 = v111;   // resolved carry
            }
        } else {
            // slow path: per-corner predicated loads (borders), no sharing
            #pragma unroll
            for (int j = 0; j < KB; ++j) {
                int x0 = x0A[j], y0 = y0A[j], z0 = z0A[j];
                const float* vb = vbA[j];
                int vx0 = ((unsigned)x0 < (unsigned)VD);
                int vx1 = ((unsigned)(x0 + 1) < (unsigned)VD);
                int vy0 = ((unsigned)y0 < (unsigned)VD);
                int vy1 = ((unsigned)(y0 + 1) < (unsigned)VD);
                int vz0 = ((unsigned)z0 < (unsigned)VD);
                int vz1 = ((unsigned)(z0 + 1) < (unsigned)VD);
                int p00 = vz0 & vy0, p01 = vz0 & vy1, p10 = vz1 & vy0, p11 = vz1 & vy1;
                float v000 = (p00 & vx0) ? __ldg(vb)                : 0.0f;
                float v001 = (p00 & vx1) ? __ldg(vb + 1)            : 0.0f;
                float v010 = (p01 & vx0) ? __ldg(vb + VD)           : 0.0f;
                float v011 = (p01 & vx1) ? __ldg(vb + VD + 1)       : 0.0f;
                float v100 = (p10 & vx0) ? __ldg(vb + VD2)          : 0.0f;
                float v101 = (p10 & vx1) ? __ldg(vb + VD2 + 1)      : 0.0f;
                float v110 = (p11 & vx0) ? __ldg(vb + VD2 + VD)     : 0.0f;
                float v111 = (p11 & vx1) ? __ldg(vb + VD2 + VD + 1) : 0.0f;
                float ax = axA[j], ay = ayA[j], az = azA[j];
                float c00 = fmaf(v001 - v000, ax, v000);
                float c01 = fmaf(v011 - v010, ax, v010);
                float c10 = fmaf(v101 - v100, ax, v100);
                float c11 = fmaf(v111 - v110, ax, v110);
                float c0  = fmaf(c01 - c00, ay, c00);
                float c1  = fmaf(c11 - c10, ay, c10);
                op[(b + j) * OD * OD] = fmaf(c1 - c0, az, c0);
                pb0 = v100; pb1 = v101; pb2 = v110; pb3 = v111;
            }
        }
        xp = x0A[KB - 1]; yp = y0A[KB - 1]; zp = z0A[KB - 1];
    }
}

// ---------------------------------------------------------------------------
extern "C" void kernel_launch(void* const* d_in, const int* in_sizes, int n_in,
                              void* d_out, int out_size) {
    const float* vol   = (const float*)d_in[0];
    const float* rot   = (const float*)d_in[1];
    const float* scale = (const float*)d_in[2];
    const float* shift = (const float*)d_in[3];
    const float* dz    = (const float*)d_in[4];
    const float* dy    = (const float*)d_in[5];
    const float* dx    = (const float*)d_in[6];
    float* out = (float*)d_out;

    prep_kernel<<<3, 1024>>>(rot, scale, shift, dz, dy, dx);

    dim3 grid(1, OD, NBATCH * (OD / KZ));
    sample_kernel<<<grid, 128>>>(vol, out);
}